// round 5
// baseline (speedup 1.0000x reference)
#include <cuda_runtime.h>
#include <math.h>

#define Bn  8
#define Sn  1024
#define Dn  1024
#define Hn  16
#define DKn 64
#define QT  16      // queries per attention block
#define VSTR 260    // padded V^T row stride (floats), 16B aligned, conflict-free

// ---------------- scratch (device globals; no allocation allowed) -------------
__device__ float g_q  [Bn*Sn*Dn];
__device__ float g_k  [Bn*Sn*Dn];
__device__ float g_v  [Bn*Sn*Dn];
__device__ float g_ctx[Bn*Sn*Dn];
__device__ float g_res[Bn*Sn*Dn];
__device__ double g_part[Bn*32*2];
__device__ float g_stats[Bn*2];

// =============================================================================
// Fused QKV projection GEMM (double-buffered SMEM).
//   X:[8192,1024] (row-major), W' logical [1024, 3072] where
//   W'[d][n] = w{q,k,v}[h = (n%1024)/64][d][n%64]
//   Output: g_q/g_k/g_v in [B*S, D] layout (feature = h*64 + k).
// 128x128x16 tile, 256 threads, 8x8 per thread, 1 barrier per k-step.
// =============================================================================
__global__ __launch_bounds__(256) void qkv_gemm_k(
    const float* __restrict__ X,
    const float* __restrict__ WQ,
    const float* __restrict__ WK,
    const float* __restrict__ WV)
{
    __shared__ float As[2][16][128];
    __shared__ float Bs[2][16][128];

    const int tid = threadIdx.x;
    const int bx  = blockIdx.x;   // 0..23 (N tiles over 3072)
    const int by  = blockIdx.y;   // 0..63 (M tiles over 8192)

    const float* W   = (bx < 8) ? WQ : (bx < 16 ? WK : WV);
    float*       OUT = (bx < 8) ? g_q : (bx < 16 ? g_k : g_v);
    const int n0 = (bx % 8) * 128;        // within [0,1024)
    const int m0 = by * 128;

    // B loader: W'[d][n] = W[(n/64)*Dn*64 + d*64 + (n%64)]
    const int brow = tid / 32;            // 0..7 (and +8)
    const int bcol = (tid % 32) * 4;      // 0..124
    const int n    = n0 + bcol;
    const float* wbase = W + (size_t)(n / 64) * (Dn * 64) + (n % 64);

    // A loader
    const int arow = tid / 4;             // 0..63 (and +64)
    const int acol = (tid % 4) * 4;
    const float* abase = X + (size_t)(m0 + arow) * Dn + acol;

    const int tx = tid % 16, ty = tid / 16;

    float acc[8][8];
    #pragma unroll
    for (int i = 0; i < 8; i++)
        #pragma unroll
        for (int j = 0; j < 8; j++) acc[i][j] = 0.f;

    // ---- prologue: load k-slice 0 into buffer 0 ----
    {
        #pragma unroll
        for (int i = 0; i < 2; i++) {
            float4 a = *(const float4*)(abase + (size_t)i * 64 * Dn);
            int r = arow + i * 64;
            As[0][acol + 0][r] = a.x; As[0][acol + 1][r] = a.y;
            As[0][acol + 2][r] = a.z; As[0][acol + 3][r] = a.w;
        }
        #pragma unroll
        for (int i = 0; i < 2; i++) {
            int d = brow + i * 8;
            float4 bv = *(const float4*)(wbase + (size_t)d * 64);
            *(float4*)&Bs[0][brow + i * 8][bcol] = bv;
        }
    }
    __syncthreads();

    int buf = 0;
    for (int k0 = 0; k0 < Dn; k0 += 16) {
        const int nk = k0 + 16;
        float4 apf[2], bpf[2];
        if (nk < Dn) {
            #pragma unroll
            for (int i = 0; i < 2; i++)
                apf[i] = *(const float4*)(abase + (size_t)i * 64 * Dn + nk);
            #pragma unroll
            for (int i = 0; i < 2; i++)
                bpf[i] = *(const float4*)(wbase + (size_t)(nk + brow + i * 8) * 64);
        }

        #pragma unroll
        for (int kk = 0; kk < 16; kk++) {
            float af[8], bf[8];
            *(float4*)&af[0] = *(const float4*)&As[buf][kk][ty * 8];
            *(float4*)&af[4] = *(const float4*)&As[buf][kk][ty * 8 + 4];
            *(float4*)&bf[0] = *(const float4*)&Bs[buf][kk][tx * 8];
            *(float4*)&bf[4] = *(const float4*)&Bs[buf][kk][tx * 8 + 4];
            #pragma unroll
            for (int i = 0; i < 8; i++)
                #pragma unroll
                for (int j = 0; j < 8; j++)
                    acc[i][j] += af[i] * bf[j];
        }

        if (nk < Dn) {
            const int nb = buf ^ 1;
            #pragma unroll
            for (int i = 0; i < 2; i++) {
                int r = arow + i * 64;
                As[nb][acol + 0][r] = apf[i].x; As[nb][acol + 1][r] = apf[i].y;
                As[nb][acol + 2][r] = apf[i].z; As[nb][acol + 3][r] = apf[i].w;
            }
            #pragma unroll
            for (int i = 0; i < 2; i++)
                *(float4*)&Bs[nb][brow + i * 8][bcol] = bpf[i];
            __syncthreads();
            buf = nb;
        }
    }

    #pragma unroll
    for (int i = 0; i < 8; i++) {
        int m = m0 + ty * 8 + i;
        float* o = OUT + (size_t)m * Dn + n0 + tx * 8;
        *(float4*)(o)     = make_float4(acc[i][0], acc[i][1], acc[i][2], acc[i][3]);
        *(float4*)(o + 4) = make_float4(acc[i][4], acc[i][5], acc[i][6], acc[i][7]);
    }
}

// =============================================================================
// Output projection GEMM (double-buffered) with residual epilogue:
//   g_res = g_ctx @ wo + X
// =============================================================================
__global__ __launch_bounds__(256) void out_gemm_k(
    const float* __restrict__ WO,
    const float* __restrict__ X)
{
    __shared__ float As[2][16][128];
    __shared__ float Bs[2][16][128];

    const int tid = threadIdx.x;
    const int bx  = blockIdx.x;   // 0..7
    const int by  = blockIdx.y;   // 0..63
    const int n0 = bx * 128;
    const int m0 = by * 128;

    const int brow = tid / 32;
    const int bcol = (tid % 32) * 4;
    const float* wbase = WO + n0 + bcol;

    const int arow = tid / 4;
    const int acol = (tid % 4) * 4;
    const float* abase = g_ctx + (size_t)(m0 + arow) * Dn + acol;

    const int tx = tid % 16, ty = tid / 16;

    float acc[8][8];
    #pragma unroll
    for (int i = 0; i < 8; i++)
        #pragma unroll
        for (int j = 0; j < 8; j++) acc[i][j] = 0.f;

    {
        #pragma unroll
        for (int i = 0; i < 2; i++) {
            float4 a = *(const float4*)(abase + (size_t)i * 64 * Dn);
            int r = arow + i * 64;
            As[0][acol + 0][r] = a.x; As[0][acol + 1][r] = a.y;
            As[0][acol + 2][r] = a.z; As[0][acol + 3][r] = a.w;
        }
        #pragma unroll
        for (int i = 0; i < 2; i++) {
            int d = brow + i * 8;
            float4 bv = *(const float4*)(wbase + (size_t)d * Dn);
            *(float4*)&Bs[0][brow + i * 8][bcol] = bv;
        }
    }
    __syncthreads();

    int buf = 0;
    for (int k0 = 0; k0 < Dn; k0 += 16) {
        const int nk = k0 + 16;
        float4 apf[2], bpf[2];
        if (nk < Dn) {
            #pragma unroll
            for (int i = 0; i < 2; i++)
                apf[i] = *(const float4*)(abase + (size_t)i * 64 * Dn + nk);
            #pragma unroll
            for (int i = 0; i < 2; i++)
                bpf[i] = *(const float4*)(wbase + (size_t)(nk + brow + i * 8) * Dn);
        }

        #pragma unroll
        for (int kk = 0; kk < 16; kk++) {
            float af[8], bf[8];
            *(float4*)&af[0] = *(const float4*)&As[buf][kk][ty * 8];
            *(float4*)&af[4] = *(const float4*)&As[buf][kk][ty * 8 + 4];
            *(float4*)&bf[0] = *(const float4*)&Bs[buf][kk][tx * 8];
            *(float4*)&bf[4] = *(const float4*)&Bs[buf][kk][tx * 8 + 4];
            #pragma unroll
            for (int i = 0; i < 8; i++)
                #pragma unroll
                for (int j = 0; j < 8; j++)
                    acc[i][j] += af[i] * bf[j];
        }

        if (nk < Dn) {
            const int nb = buf ^ 1;
            #pragma unroll
            for (int i = 0; i < 2; i++) {
                int r = arow + i * 64;
                As[nb][acol + 0][r] = apf[i].x; As[nb][acol + 1][r] = apf[i].y;
                As[nb][acol + 2][r] = apf[i].z; As[nb][acol + 3][r] = apf[i].w;
            }
            #pragma unroll
            for (int i = 0; i < 2; i++)
                *(float4*)&Bs[nb][brow + i * 8][bcol] = bpf[i];
            __syncthreads();
            buf = nb;
        }
    }

    #pragma unroll
    for (int i = 0; i < 8; i++) {
        int m = m0 + ty * 8 + i;
        size_t off = (size_t)m * Dn + n0 + tx * 8;
        float4 x0 = *(const float4*)(X + off);
        float4 x1 = *(const float4*)(X + off + 4);
        float4 r0 = make_float4(acc[i][0] + x0.x, acc[i][1] + x0.y,
                                acc[i][2] + x0.z, acc[i][3] + x0.w);
        float4 r1 = make_float4(acc[i][4] + x1.x, acc[i][5] + x1.y,
                                acc[i][6] + x1.z, acc[i][7] + x1.w);
        *(float4*)(g_res + off)     = r0;
        *(float4*)(g_res + off + 4) = r1;
    }
}

// =============================================================================
// Attention: one block = (b, h, 16-query tile). Scores [16][1024] in SMEM,
// masked + softmax in SMEM, then PV with V^T chunks staged in SMEM.
// =============================================================================
__global__ __launch_bounds__(256) void attn_k(const int* __restrict__ mask)
{
    extern __shared__ float sh[];
    float* sQ  = sh;                       // QT*64
    float* sS  = sh + QT * 64;             // QT*Sn
    float* sVT = sS + QT * Sn;             // 64*VSTR

    const int tid  = threadIdx.x;
    const int blk  = blockIdx.x;
    const int tile = blk % (Sn / QT);
    const int h    = (blk / (Sn / QT)) % Hn;
    const int b    = blk / ((Sn / QT) * Hn);
    const int s0   = tile * QT;

    // load Q tile
    {
        int j  = tid / 16;
        int d4 = (tid % 16) * 4;
        const float* qp = g_q + ((size_t)(b * Sn + s0 + j)) * Dn + h * DKn + d4;
        *(float4*)&sQ[j * 64 + d4] = *(const float4*)qp;
    }
    __syncthreads();

    // ---- phase 1: scores = (Q K^T) * scale, masked -------------------------
    const float scale = 0.125f; // 1/sqrt(64)
    for (int c = 0; c < 4; c++) {
        const int t = c * 256 + tid;
        const float* kp = g_k + ((size_t)(b * Sn + t)) * Dn + h * DKn;
        float kreg[64];
        #pragma unroll
        for (int i = 0; i < 16; i++)
            *(float4*)&kreg[i * 4] = *(const float4*)(kp + i * 4);

        #pragma unroll
        for (int j = 0; j < QT; j++) {
            float s = 0.f;
            #pragma unroll
            for (int i = 0; i < 16; i++) {
                float4 qv = *(const float4*)&sQ[j * 64 + i * 4];
                s += qv.x * kreg[i * 4 + 0];
                s += qv.y * kreg[i * 4 + 1];
                s += qv.z * kreg[i * 4 + 2];
                s += qv.w * kreg[i * 4 + 3];
            }
            int m = mask[((size_t)(b * Sn) + (s0 + j)) * Sn + t];
            sS[j * Sn + t] = (m != 0) ? s * scale : -1e9f;
        }
    }
    __syncthreads();

    // ---- phase 2: softmax rows (warp w handles rows 2w, 2w+1) --------------
    const int w = tid / 32, lane = tid % 32;
    #pragma unroll
    for (int rr = 0; rr < 2; rr++) {
        float* row = &sS[(w * 2 + rr) * Sn];
        float mx = -1e30f;
        #pragma unroll
        for (int i = 0; i < 32; i++) mx = fmaxf(mx, row[lane + i * 32]);
        #pragma unroll
        for (int o = 16; o > 0; o >>= 1)
            mx = fmaxf(mx, __shfl_xor_sync(0xffffffffu, mx, o));
        float sum = 0.f;
        #pragma unroll
        for (int i = 0; i < 32; i++) {
            float p = __expf(row[lane + i * 32] - mx);
            row[lane + i * 32] = p;
            sum += p;
        }
        #pragma unroll
        for (int o = 16; o > 0; o >>= 1)
            sum += __shfl_xor_sync(0xffffffffu, sum, o);
        float inv = 1.f / sum;
        #pragma unroll
        for (int i = 0; i < 32; i++) row[lane + i * 32] *= inv;
    }

    // ---- phase 3: ctx = P @ V ----------------------------------------------
    float a00 = 0.f, a01 = 0.f, a10 = 0.f, a11 = 0.f;
    const int q0 = w * 2, d0 = lane, d1 = lane + 32;

    for (int c = 0; c < 4; c++) {
        __syncthreads();     // previous chunk consumers done (and phase-2 done)
        {
            const int t = c * 256 + tid;
            const float* vp = g_v + ((size_t)(b * Sn + t)) * Dn + h * DKn;
            #pragma unroll
            for (int i = 0; i < 16; i++) {
                float4 v = *(const float4*)(vp + i * 4);
                sVT[(i * 4 + 0) * VSTR + tid] = v.x;
                sVT[(i * 4 + 1) * VSTR + tid] = v.y;
                sVT[(i * 4 + 2) * VSTR + tid] = v.z;
                sVT[(i * 4 + 3) * VSTR + tid] = v.w;
            }
        }
        __syncthreads();

        const float* P0 = &sS[q0 * Sn + c * 256];
        const float* P1 = &sS[(q0 + 1) * Sn + c * 256];
        const float* V0 = &sVT[(size_t)d0 * VSTR];
        const float* V1 = &sVT[(size_t)d1 * VSTR];
        #pragma unroll 8
        for (int kk = 0; kk < 256; kk += 4) {
            float4 p0 = *(const float4*)(P0 + kk);
            float4 p1 = *(const float4*)(P1 + kk);
            float4 v0 = *(const float4*)(V0 + kk);
            float4 v1 = *(const float4*)(V1 + kk);
            a00 += p0.x * v0.x + p0.y * v0.y + p0.z * v0.z + p0.w * v0.w;
            a01 += p0.x * v1.x + p0.y * v1.y + p0.z * v1.z + p0.w * v1.w;
            a10 += p1.x * v0.x + p1.y * v0.y + p1.z * v0.z + p1.w * v0.w;
            a11 += p1.x * v1.x + p1.y * v1.y + p1.z * v1.z + p1.w * v1.w;
        }
    }

    float* cp = g_ctx + ((size_t)(b * Sn + s0 + q0)) * Dn + h * DKn;
    cp[d0]      = a00;
    cp[d1]      = a01;
    cp[Dn + d0] = a10;
    cp[Dn + d1] = a11;
}

// =============================================================================
// LayerNorm over (S, D) per batch: partial sums -> finish -> normalize
// =============================================================================
__global__ __launch_bounds__(256) void ln_partial_k()
{
    const int blk = blockIdx.x;     // Bn*32
    const int b   = blk / 32;
    const int seg = blk % 32;
    const float* base = g_res + (size_t)b * Sn * Dn + (size_t)seg * 32768;

    float s = 0.f, s2 = 0.f;
    for (int i = threadIdx.x; i < 32768; i += 256) {
        float v = base[i];
        s += v;
        s2 += v * v;
    }
    __shared__ double sh1[256], sh2[256];
    sh1[threadIdx.x] = (double)s;
    sh2[threadIdx.x] = (double)s2;
    __syncthreads();
    for (int o = 128; o > 0; o >>= 1) {
        if (threadIdx.x < o) {
            sh1[threadIdx.x] += sh1[threadIdx.x + o];
            sh2[threadIdx.x] += sh2[threadIdx.x + o];
        }
        __syncthreads();
    }
    if (threadIdx.x == 0) {
        g_part[blk * 2 + 0] = sh1[0];
        g_part[blk * 2 + 1] = sh2[0];
    }
}

__global__ void ln_finish_k()
{
    const int b = blockIdx.x;
    const int l = threadIdx.x;   // 32 threads
    __shared__ double sh[64];
    sh[l]      = g_part[(b * 32 + l) * 2 + 0];
    sh[32 + l] = g_part[(b * 32 + l) * 2 + 1];
    __syncthreads();
    if (l == 0) {
        double S = 0.0, S2 = 0.0;
        for (int i = 0; i < 32; i++) { S += sh[i]; S2 += sh[32 + i]; }
        const double N = (double)Sn * (double)Dn;
        double mean = S / N;
        double var  = S2 / N - mean * mean;
        g_stats[b * 2 + 0] = (float)mean;
        g_stats[b * 2 + 1] = (float)(1.0 / sqrt(var + 1e-5));
    }
}

__global__ __launch_bounds__(256) void ln_norm_k(float* __restrict__ out)
{
    const int idx = blockIdx.x * 256 + threadIdx.x;
    const size_t i4 = (size_t)idx * 4;
    const int b = (int)(i4 >> 20);   // Sn*Dn = 2^20
    const float mean = g_stats[b * 2 + 0];
    const float istd = g_stats[b * 2 + 1];
    float4 v = *(const float4*)&g_res[i4];
    v.x = (v.x - mean) * istd;
    v.y = (v.y - mean) * istd;
    v.z = (v.z - mean) * istd;
    v.w = (v.w - mean) * istd;
    *(float4*)&out[i4] = v;
}

// =============================================================================
extern "C" void kernel_launch(void* const* d_in, const int* in_sizes, int n_in,
                              void* d_out, int out_size)
{
    const int*   mask = (const int*)  d_in[0];
    const float* x    = (const float*)d_in[1];
    const float* wq   = (const float*)d_in[2];
    const float* wk   = (const float*)d_in[3];
    const float* wv   = (const float*)d_in[4];
    const float* wo   = (const float*)d_in[5];
    float* out = (float*)d_out;

    // 1) fused QKV projection
    qkv_gemm_k<<<dim3(24, 64), 256>>>(x, wq, wk, wv);

    // 2) attention
    const int smem_attn = (QT * 64 + QT * Sn + 64 * VSTR) * (int)sizeof(float);
    cudaFuncSetAttribute(attn_k, cudaFuncAttributeMaxDynamicSharedMemorySize, smem_attn);
    attn_k<<<Bn * Hn * (Sn / QT), 256, smem_attn>>>(mask);

    // 3) output projection + residual
    out_gemm_k<<<dim3(8, 64), 256>>>(wo, x);

    // 4) layernorm over (S, D) per batch
    ln_partial_k<<<Bn * 32, 256>>>();
    ln_finish_k<<<Bn, 32>>>();
    ln_norm_k<<<(Bn * Sn * Dn) / (256 * 4), 256>>>(out);
}

// round 7
// speedup vs baseline: 1.0666x; 1.0666x over previous
#include <cuda_runtime.h>
#include <cuda_bf16.h>
#include <math.h>
#include <stdint.h>

#define Bn  8
#define Sn  1024
#define Dn  1024
#define Hn  16
#define DKn 64
#define QT  16
#define VSTR 260

// ---------------- scratch (device globals; no allocation allowed) -------------
__device__ __align__(256) float g_q  [Bn*Sn*Dn];
__device__ __align__(256) float g_k  [Bn*Sn*Dn];
__device__ __align__(256) float g_v  [Bn*Sn*Dn];
__device__ __align__(256) float g_ctx[Bn*Sn*Dn];
__device__ __align__(256) float g_res[Bn*Sn*Dn];
__device__ double g_part[Bn*32*2];
__device__ float g_stats[Bn*2];

// bf16 split scratch
__device__ __align__(256) __nv_bfloat16 g_xhi[Bn*Sn*Dn];
__device__ __align__(256) __nv_bfloat16 g_xlo[Bn*Sn*Dn];
__device__ __align__(256) __nv_bfloat16 g_chi[Bn*Sn*Dn];
__device__ __align__(256) __nv_bfloat16 g_clo[Bn*Sn*Dn];
__device__ __align__(256) __nv_bfloat16 g_bthi[3*Dn*Dn];   // qkv weights, Bt[n][k]
__device__ __align__(256) __nv_bfloat16 g_btlo[3*Dn*Dn];
__device__ __align__(256) __nv_bfloat16 g_wohi[Dn*Dn];     // wo^T, Bt[n][k]=WO[k][n]
__device__ __align__(256) __nv_bfloat16 g_wolo[Dn*Dn];

// ---------------- mma.sync helper (sm_80+ path, compiles on compute_103) ------
__device__ __forceinline__ void mma16816(float* c, const uint32_t* a, const uint32_t* b)
{
    asm volatile(
        "mma.sync.aligned.m16n8k16.row.col.f32.bf16.bf16.f32 "
        "{%0,%1,%2,%3}, {%4,%5,%6,%7}, {%8,%9}, {%0,%1,%2,%3};"
        : "+f"(c[0]), "+f"(c[1]), "+f"(c[2]), "+f"(c[3])
        : "r"(a[0]), "r"(a[1]), "r"(a[2]), "r"(a[3]), "r"(b[0]), "r"(b[1]));
}

// ======================== conversion kernels =================================
__global__ __launch_bounds__(256) void cvt_split_k(const float* __restrict__ xext, int which)
{
    const float* src = which ? g_ctx : xext;
    __nv_bfloat16* hi = which ? g_chi : g_xhi;
    __nv_bfloat16* lo = which ? g_clo : g_xlo;
    size_t i = ((size_t)blockIdx.x * 256 + threadIdx.x) * 4;
    float4 v = *(const float4*)(src + i);
    __nv_bfloat16 h0 = __float2bfloat16(v.x), l0 = __float2bfloat16(v.x - __bfloat162float(h0));
    __nv_bfloat16 h1 = __float2bfloat16(v.y), l1 = __float2bfloat16(v.y - __bfloat162float(h1));
    __nv_bfloat16 h2 = __float2bfloat16(v.z), l2 = __float2bfloat16(v.z - __bfloat162float(h2));
    __nv_bfloat16 h3 = __float2bfloat16(v.w), l3 = __float2bfloat16(v.w - __bfloat162float(h3));
    *(__nv_bfloat162*)(hi + i)     = __halves2bfloat162(h0, h1);
    *(__nv_bfloat162*)(hi + i + 2) = __halves2bfloat162(h2, h3);
    *(__nv_bfloat162*)(lo + i)     = __halves2bfloat162(l0, l1);
    *(__nv_bfloat162*)(lo + i + 2) = __halves2bfloat162(l2, l3);
}

// Bt_qkv[n][k] = Wsel[h][k][kk], n in [0,3072), h=(n%1024)/64, kk=n%64
__global__ __launch_bounds__(256) void cvt_wqkv_k(const float* __restrict__ WQ,
                                                  const float* __restrict__ WK,
                                                  const float* __restrict__ WV)
{
    size_t idx = (size_t)blockIdx.x * 256 + threadIdx.x;   // over 3072*1024
    int k = (int)(idx & 1023);
    int n = (int)(idx >> 10);
    int within = n & 1023, sel = n >> 10;
    const float* W = (sel == 0) ? WQ : (sel == 1 ? WK : WV);
    float w = W[(size_t)(within >> 6) * (Dn * DKn) + (size_t)k * DKn + (within & 63)];
    __nv_bfloat16 h = __float2bfloat16(w);
    g_bthi[idx] = h;
    g_btlo[idx] = __float2bfloat16(w - __bfloat162float(h));
}

// Bt_wo[n][k] = WO[k][n]  (tiled transpose + split)
__global__ __launch_bounds__(256) void cvt_wo_k(const float* __restrict__ WO)
{
    __shared__ float t[32][33];
    const int x = threadIdx.x, y = threadIdx.y;       // (32, 8)
    const int bx = blockIdx.x, by = blockIdx.y;
    #pragma unroll
    for (int i = 0; i < 4; i++)
        t[y + i * 8][x] = WO[(size_t)(by * 32 + y + i * 8) * Dn + bx * 32 + x];
    __syncthreads();
    #pragma unroll
    for (int i = 0; i < 4; i++) {
        float w = t[x][y + i * 8];
        __nv_bfloat16 h = __float2bfloat16(w);
        size_t o = (size_t)(bx * 32 + y + i * 8) * Dn + by * 32 + x;
        g_wohi[o] = h;
        g_wolo[o] = __float2bfloat16(w - __bfloat162float(h));
    }
}

// ======================== split-bf16 HMMA GEMM ===============================
// C[M x N] = A * Bt^T (Bt is [N][K] K-major). 128x128 tile, 8 warps (2x4),
// warp tile 64x32 (4x4 m16n8k16 frags), K-step 16, double-buffered SMEM.
// 3-pass split accumulate: Ahi*Bhi + Ahi*Blo + Alo*Bhi (fp32 accum).
// mode 0: qkv (OUT among g_q/g_k/g_v by n block); mode 1: out proj + residual.
__global__ __launch_bounds__(256, 1) void gemm_mma_k(const float* __restrict__ Xres, int mode)
{
    __shared__ __align__(16) __nv_bfloat16 sA[2][2][128 * 16];
    __shared__ __align__(16) __nv_bfloat16 sB[2][2][128 * 16];

    const int tid  = threadIdx.x;
    const int wid  = tid >> 5, lane = tid & 31;
    const int g    = lane >> 2, tg = lane & 3;
    const int m0   = blockIdx.y * 128;
    const int n0g  = blockIdx.x * 128;
    const int mo   = (wid >> 2) * 64;     // warp row offset in tile
    const int no   = (wid & 3) * 32;      // warp col offset in tile

    const __nv_bfloat16* Ahi = mode ? g_chi : g_xhi;
    const __nv_bfloat16* Alo = mode ? g_clo : g_xlo;
    const __nv_bfloat16* Bhi = mode ? g_wohi : g_bthi;
    const __nv_bfloat16* Blo = mode ? g_wolo : g_btlo;

    // loaders: thread covers one 8-bf16 segment; row = tid/2, seg = (tid&1)*8
    const int lrow = tid >> 1;
    const int lseg = (tid & 1) * 8;
    const __nv_bfloat16* pAhi = Ahi + (size_t)(m0 + lrow) * Dn + lseg;
    const __nv_bfloat16* pAlo = Alo + (size_t)(m0 + lrow) * Dn + lseg;
    const __nv_bfloat16* pBhi = Bhi + (size_t)(n0g + lrow) * Dn + lseg;
    const __nv_bfloat16* pBlo = Blo + (size_t)(n0g + lrow) * Dn + lseg;
    const int soff = lrow * 16 + lseg;

    float c[4][4][4];
    #pragma unroll
    for (int i = 0; i < 4; i++)
        #pragma unroll
        for (int j = 0; j < 4; j++)
            #pragma unroll
            for (int r = 0; r < 4; r++) c[i][j][r] = 0.f;

    // prologue: stage 0
    *(uint4*)&sA[0][0][soff] = *(const uint4*)pAhi;
    *(uint4*)&sA[0][1][soff] = *(const uint4*)pAlo;
    *(uint4*)&sB[0][0][soff] = *(const uint4*)pBhi;
    *(uint4*)&sB[0][1][soff] = *(const uint4*)pBlo;
    __syncthreads();

    const int NK = Dn / 16;   // 64
    for (int ks = 0; ks < NK; ks++) {
        const int cur = ks & 1;

        uint4 va, vb, vc, vd;
        if (ks < NK - 1) {
            const int k0 = (ks + 1) * 16;
            va = *(const uint4*)(pAhi + k0);
            vb = *(const uint4*)(pAlo + k0);
            vc = *(const uint4*)(pBhi + k0);
            vd = *(const uint4*)(pBlo + k0);
        }

        // load fragments
        uint32_t a[2][4][4];
        #pragma unroll
        for (int sp = 0; sp < 2; sp++) {
            const __nv_bfloat16* base = &sA[cur][sp][0];
            #pragma unroll
            for (int i = 0; i < 4; i++) {
                int r = (mo + i * 16 + g) * 16 + tg * 2;
                a[sp][i][0] = *(const uint32_t*)&base[r];
                a[sp][i][1] = *(const uint32_t*)&base[r + 8 * 16];
                a[sp][i][2] = *(const uint32_t*)&base[r + 8];
                a[sp][i][3] = *(const uint32_t*)&base[r + 8 * 16 + 8];
            }
        }
        uint32_t b[2][4][2];
        #pragma unroll
        for (int sp = 0; sp < 2; sp++) {
            const __nv_bfloat16* base = &sB[cur][sp][0];
            #pragma unroll
            for (int j = 0; j < 4; j++) {
                int r = (no + j * 8 + g) * 16 + tg * 2;
                b[sp][j][0] = *(const uint32_t*)&base[r];
                b[sp][j][1] = *(const uint32_t*)&base[r + 8];
            }
        }

        // 3-pass MMAs
        #pragma unroll
        for (int i = 0; i < 4; i++)
            #pragma unroll
            for (int j = 0; j < 4; j++) {
                mma16816(c[i][j], a[0][i], b[0][j]);   // hi*hi
                mma16816(c[i][j], a[0][i], b[1][j]);   // hi*lo
                mma16816(c[i][j], a[1][i], b[0][j]);   // lo*hi
            }

        if (ks < NK - 1) {
            const int nb = cur ^ 1;
            *(uint4*)&sA[nb][0][soff] = va;
            *(uint4*)&sA[nb][1][soff] = vb;
            *(uint4*)&sB[nb][0][soff] = vc;
            *(uint4*)&sB[nb][1][soff] = vd;
            __syncthreads();
        }
    }

    // epilogue
    float* OUT;
    int nbase;
    if (mode == 0) {
        int sel = n0g >> 10;
        OUT = (sel == 0) ? g_q : (sel == 1 ? g_k : g_v);
        nbase = n0g & 1023;
    } else {
        OUT = g_res;
        nbase = n0g;
    }

    #pragma unroll
    for (int i = 0; i < 4; i++) {
        #pragma unroll
        for (int j = 0; j < 4; j++) {
            const int r0  = m0 + mo + i * 16 + g;
            const int col = nbase + no + j * 8 + tg * 2;
            size_t o0 = (size_t)r0 * Dn + col;
            size_t o1 = (size_t)(r0 + 8) * Dn + col;
            float2 v0 = make_float2(c[i][j][0], c[i][j][1]);
            float2 v1 = make_float2(c[i][j][2], c[i][j][3]);
            if (mode == 1) {
                float2 x0 = *(const float2*)(Xres + o0);
                float2 x1 = *(const float2*)(Xres + o1);
                v0.x += x0.x; v0.y += x0.y;
                v1.x += x1.x; v1.y += x1.y;
            }
            *(float2*)(OUT + o0) = v0;
            *(float2*)(OUT + o1) = v1;
        }
    }
}

// ======================== attention (unchanged) ==============================
__global__ __launch_bounds__(256) void attn_k(const int* __restrict__ mask)
{
    extern __shared__ float sh[];
    float* sQ  = sh;
    float* sS  = sh + QT * 64;
    float* sVT = sS + QT * Sn;

    const int tid  = threadIdx.x;
    const int blk  = blockIdx.x;
    const int tile = blk % (Sn / QT);
    const int h    = (blk / (Sn / QT)) % Hn;
    const int b    = blk / ((Sn / QT) * Hn);
    const int s0   = tile * QT;

    {
        int j  = tid / 16;
        int d4 = (tid % 16) * 4;
        const float* qp = g_q + ((size_t)(b * Sn + s0 + j)) * Dn + h * DKn + d4;
        *(float4*)&sQ[j * 64 + d4] = *(const float4*)qp;
    }
    __syncthreads();

    const float scale = 0.125f;
    for (int c = 0; c < 4; c++) {
        const int t = c * 256 + tid;
        const float* kp = g_k + ((size_t)(b * Sn + t)) * Dn + h * DKn;
        float kreg[64];
        #pragma unroll
        for (int i = 0; i < 16; i++)
            *(float4*)&kreg[i * 4] = *(const float4*)(kp + i * 4);

        #pragma unroll
        for (int j = 0; j < QT; j++) {
            float s = 0.f;
            #pragma unroll
            for (int i = 0; i < 16; i++) {
                float4 qv = *(const float4*)&sQ[j * 64 + i * 4];
                s += qv.x * kreg[i * 4 + 0];
                s += qv.y * kreg[i * 4 + 1];
                s += qv.z * kreg[i * 4 + 2];
                s += qv.w * kreg[i * 4 + 3];
            }
            int m = mask[((size_t)(b * Sn) + (s0 + j)) * Sn + t];
            sS[j * Sn + t] = (m != 0) ? s * scale : -1e9f;
        }
    }
    __syncthreads();

    const int w = tid / 32, lane = tid % 32;
    #pragma unroll
    for (int rr = 0; rr < 2; rr++) {
        float* row = &sS[(w * 2 + rr) * Sn];
        float mx = -1e30f;
        #pragma unroll
        for (int i = 0; i < 32; i++) mx = fmaxf(mx, row[lane + i * 32]);
        #pragma unroll
        for (int o = 16; o > 0; o >>= 1)
            mx = fmaxf(mx, __shfl_xor_sync(0xffffffffu, mx, o));
        float sum = 0.f;
        #pragma unroll
        for (int i = 0; i < 32; i++) {
            float p = __expf(row[lane + i * 32] - mx);
            row[lane + i * 32] = p;
            sum += p;
        }
        #pragma unroll
        for (int o = 16; o > 0; o >>= 1)
            sum += __shfl_xor_sync(0xffffffffu, sum, o);
        float inv = 1.f / sum;
        #pragma unroll
        for (int i = 0; i < 32; i++) row[lane + i * 32] *= inv;
    }

    float a00 = 0.f, a01 = 0.f, a10 = 0.f, a11 = 0.f;
    const int q0 = w * 2, d0 = lane, d1 = lane + 32;

    for (int c = 0; c < 4; c++) {
        __syncthreads();
        {
            const int t = c * 256 + tid;
            const float* vp = g_v + ((size_t)(b * Sn + t)) * Dn + h * DKn;
            #pragma unroll
            for (int i = 0; i < 16; i++) {
                float4 v = *(const float4*)(vp + i * 4);
                sVT[(i * 4 + 0) * VSTR + tid] = v.x;
                sVT[(i * 4 + 1) * VSTR + tid] = v.y;
                sVT[(i * 4 + 2) * VSTR + tid] = v.z;
                sVT[(i * 4 + 3) * VSTR + tid] = v.w;
            }
        }
        __syncthreads();

        const float* P0 = &sS[q0 * Sn + c * 256];
        const float* P1 = &sS[(q0 + 1) * Sn + c * 256];
        const float* V0 = &sVT[(size_t)d0 * VSTR];
        const float* V1 = &sVT[(size_t)d1 * VSTR];
        #pragma unroll 8
        for (int kk = 0; kk < 256; kk += 4) {
            float4 p0 = *(const float4*)(P0 + kk);
            float4 p1 = *(const float4*)(P1 + kk);
            float4 v0 = *(const float4*)(V0 + kk);
            float4 v1 = *(const float4*)(V1 + kk);
            a00 += p0.x * v0.x + p0.y * v0.y + p0.z * v0.z + p0.w * v0.w;
            a01 += p0.x * v1.x + p0.y * v1.y + p0.z * v1.z + p0.w * v1.w;
            a10 += p1.x * v0.x + p1.y * v0.y + p1.z * v0.z + p1.w * v0.w;
            a11 += p1.x * v1.x + p1.y * v1.y + p1.z * v1.z + p1.w * v1.w;
        }
    }

    float* cp = g_ctx + ((size_t)(b * Sn + s0 + q0)) * Dn + h * DKn;
    cp[d0]      = a00;
    cp[d1]      = a01;
    cp[Dn + d0] = a10;
    cp[Dn + d1] = a11;
}

// ======================== LayerNorm ==========================================
__global__ __launch_bounds__(256) void ln_partial_k()
{
    const int blk = blockIdx.x;
    const int b   = blk / 32;
    const int seg = blk % 32;
    const float* base = g_res + (size_t)b * Sn * Dn + (size_t)seg * 32768;

    float s = 0.f, s2 = 0.f;
    for (int i = threadIdx.x; i < 32768; i += 256) {
        float v = base[i];
        s += v;
        s2 += v * v;
    }
    __shared__ double sh1[256], sh2[256];
    sh1[threadIdx.x] = (double)s;
    sh2[threadIdx.x] = (double)s2;
    __syncthreads();
    for (int o = 128; o > 0; o >>= 1) {
        if (threadIdx.x < o) {
            sh1[threadIdx.x] += sh1[threadIdx.x + o];
            sh2[threadIdx.x] += sh2[threadIdx.x + o];
        }
        __syncthreads();
    }
    if (threadIdx.x == 0) {
        g_part[blk * 2 + 0] = sh1[0];
        g_part[blk * 2 + 1] = sh2[0];
    }
}

__global__ void ln_finish_k()
{
    const int b = blockIdx.x;
    const int l = threadIdx.x;
    __shared__ double sh[64];
    sh[l]      = g_part[(b * 32 + l) * 2 + 0];
    sh[32 + l] = g_part[(b * 32 + l) * 2 + 1];
    __syncthreads();
    if (l == 0) {
        double S = 0.0, S2 = 0.0;
        for (int i = 0; i < 32; i++) { S += sh[i]; S2 += sh[32 + i]; }
        const double N = (double)Sn * (double)Dn;
        double mean = S / N;
        double var  = S2 / N - mean * mean;
        g_stats[b * 2 + 0] = (float)mean;
        g_stats[b * 2 + 1] = (float)(1.0 / sqrt(var + 1e-5));
    }
}

__global__ __launch_bounds__(256) void ln_norm_k(float* __restrict__ out)
{
    const int idx = blockIdx.x * 256 + threadIdx.x;
    const size_t i4 = (size_t)idx * 4;
    const int b = (int)(i4 >> 20);
    const float mean = g_stats[b * 2 + 0];
    const float istd = g_stats[b * 2 + 1];
    float4 v = *(const float4*)&g_res[i4];
    v.x = (v.x - mean) * istd;
    v.y = (v.y - mean) * istd;
    v.z = (v.z - mean) * istd;
    v.w = (v.w - mean) * istd;
    *(float4*)&out[i4] = v;
}

// =============================================================================
extern "C" void kernel_launch(void* const* d_in, const int* in_sizes, int n_in,
                              void* d_out, int out_size)
{
    const int*   mask = (const int*)  d_in[0];
    const float* x    = (const float*)d_in[1];
    const float* wq   = (const float*)d_in[2];
    const float* wk   = (const float*)d_in[3];
    const float* wv   = (const float*)d_in[4];
    const float* wo   = (const float*)d_in[5];
    float* out = (float*)d_out;

    const int smem_attn = (QT * 64 + QT * Sn + 64 * VSTR) * (int)sizeof(float);
    cudaFuncSetAttribute(attn_k, cudaFuncAttributeMaxDynamicSharedMemorySize, smem_attn);

    // 0) bf16 split conversions
    cvt_split_k<<<(Bn * Sn * Dn) / (256 * 4), 256>>>(x, 0);
    cvt_wqkv_k<<<(3 * Dn * Dn) / 256, 256>>>(wq, wk, wv);
    cvt_wo_k<<<dim3(Dn / 32, Dn / 32), dim3(32, 8)>>>(wo);

    // 1) fused QKV projection (HMMA split-bf16)
    gemm_mma_k<<<dim3(24, 64), 256>>>(nullptr, 0);

    // 2) attention
    attn_k<<<Bn * Hn * (Sn / QT), 256, smem_attn>>>(mask);

    // 3) output projection + residual (HMMA split-bf16)
    cvt_split_k<<<(Bn * Sn * Dn) / (256 * 4), 256>>>(nullptr, 1);
    gemm_mma_k<<<dim3(8, 64), 256>>>(x, 1);

    // 4) layernorm over (S, D) per batch
    ln_partial_k<<<Bn * 32, 256>>>();
    ln_finish_k<<<Bn, 32>>>();
    ln_norm_k<<<(Bn * Sn * Dn) / (256 * 4), 256>>>(out);
}

// round 9
// speedup vs baseline: 1.0668x; 1.0002x over previous
#include <cuda_runtime.h>
#include <cuda_bf16.h>
#include <math.h>
#include <stdint.h>

#define Bn  8
#define Sn  1024
#define Dn  1024
#define Hn  16
#define DKn 64
#define QT  16
#define VSTR 260

// ---------------- scratch (device globals; no allocation allowed) -------------
__device__ __align__(256) float g_q  [Bn*Sn*Dn];
__device__ __align__(256) float g_k  [Bn*Sn*Dn];
__device__ __align__(256) float g_v  [Bn*Sn*Dn];
__device__ __align__(256) float g_ctx[Bn*Sn*Dn];
__device__ __align__(256) float g_res[Bn*Sn*Dn];
__device__ double g_part[Bn*32*2];
__device__ float g_stats[Bn*2];

// bf16 split scratch
__device__ __align__(256) __nv_bfloat16 g_xhi[Bn*Sn*Dn];
__device__ __align__(256) __nv_bfloat16 g_xlo[Bn*Sn*Dn];
__device__ __align__(256) __nv_bfloat16 g_chi[Bn*Sn*Dn];
__device__ __align__(256) __nv_bfloat16 g_clo[Bn*Sn*Dn];
__device__ __align__(256) __nv_bfloat16 g_bthi[3*Dn*Dn];   // qkv weights, Bt[n][k]
__device__ __align__(256) __nv_bfloat16 g_btlo[3*Dn*Dn];
__device__ __align__(256) __nv_bfloat16 g_wohi[Dn*Dn];     // wo^T, Bt[n][k]=WO[k][n]
__device__ __align__(256) __nv_bfloat16 g_wolo[Dn*Dn];

// ---------------- mma.sync helper (sm_80+ path, compiles on compute_103) ------
__device__ __forceinline__ void mma16816(float* c, const uint32_t* a, const uint32_t* b)
{
    asm volatile(
        "mma.sync.aligned.m16n8k16.row.col.f32.bf16.bf16.f32 "
        "{%0,%1,%2,%3}, {%4,%5,%6,%7}, {%8,%9}, {%0,%1,%2,%3};"
        : "+f"(c[0]), "+f"(c[1]), "+f"(c[2]), "+f"(c[3])
        : "r"(a[0]), "r"(a[1]), "r"(a[2]), "r"(a[3]), "r"(b[0]), "r"(b[1]));
}

// ======================== conversion kernels =================================
__global__ __launch_bounds__(256) void cvt_split_k(const float* __restrict__ xext, int which)
{
    const float* src = which ? g_ctx : xext;
    __nv_bfloat16* hi = which ? g_chi : g_xhi;
    __nv_bfloat16* lo = which ? g_clo : g_xlo;
    size_t i = ((size_t)blockIdx.x * 256 + threadIdx.x) * 4;
    float4 v = *(const float4*)(src + i);
    __nv_bfloat16 h0 = __float2bfloat16(v.x), l0 = __float2bfloat16(v.x - __bfloat162float(h0));
    __nv_bfloat16 h1 = __float2bfloat16(v.y), l1 = __float2bfloat16(v.y - __bfloat162float(h1));
    __nv_bfloat16 h2 = __float2bfloat16(v.z), l2 = __float2bfloat16(v.z - __bfloat162float(h2));
    __nv_bfloat16 h3 = __float2bfloat16(v.w), l3 = __float2bfloat16(v.w - __bfloat162float(h3));
    *(__nv_bfloat162*)(hi + i)     = __halves2bfloat162(h0, h1);
    *(__nv_bfloat162*)(hi + i + 2) = __halves2bfloat162(h2, h3);
    *(__nv_bfloat162*)(lo + i)     = __halves2bfloat162(l0, l1);
    *(__nv_bfloat162*)(lo + i + 2) = __halves2bfloat162(l2, l3);
}

// Bt_qkv[n][k] = Wsel[h][k][kk], n in [0,3072), h=(n%1024)/64, kk=n%64
__global__ __launch_bounds__(256) void cvt_wqkv_k(const float* __restrict__ WQ,
                                                  const float* __restrict__ WK,
                                                  const float* __restrict__ WV)
{
    size_t idx = (size_t)blockIdx.x * 256 + threadIdx.x;   // over 3072*1024
    int k = (int)(idx & 1023);
    int n = (int)(idx >> 10);
    int within = n & 1023, sel = n >> 10;
    const float* W = (sel == 0) ? WQ : (sel == 1 ? WK : WV);
    float w = W[(size_t)(within >> 6) * (Dn * DKn) + (size_t)k * DKn + (within & 63)];
    __nv_bfloat16 h = __float2bfloat16(w);
    g_bthi[idx] = h;
    g_btlo[idx] = __float2bfloat16(w - __bfloat162float(h));
}

// Bt_wo[n][k] = WO[k][n]  (tiled transpose + split)
__global__ __launch_bounds__(256) void cvt_wo_k(const float* __restrict__ WO)
{
    __shared__ float t[32][33];
    const int x = threadIdx.x, y = threadIdx.y;       // (32, 8)
    const int bx = blockIdx.x, by = blockIdx.y;
    #pragma unroll
    for (int i = 0; i < 4; i++)
        t[y + i * 8][x] = WO[(size_t)(by * 32 + y + i * 8) * Dn + bx * 32 + x];
    __syncthreads();
    #pragma unroll
    for (int i = 0; i < 4; i++) {
        float w = t[x][y + i * 8];
        __nv_bfloat16 h = __float2bfloat16(w);
        size_t o = (size_t)(bx * 32 + y + i * 8) * Dn + by * 32 + x;
        g_wohi[o] = h;
        g_wolo[o] = __float2bfloat16(w - __bfloat162float(h));
    }
}

// ======================== split-bf16 HMMA GEMM ===============================
// C[M x N] = A * Bt^T (Bt is [N][K] K-major). 128x128 tile, 8 warps (2x4),
// warp tile 64x32 (4x4 m16n8k16 frags), K-step 16, double-buffered SMEM.
// 3-pass split accumulate: Ahi*Bhi + Ahi*Blo + Alo*Bhi (fp32 accum).
// mode 0: qkv (OUT among g_q/g_k/g_v by n block); mode 1: out proj + residual.
__global__ __launch_bounds__(256, 1) void gemm_mma_k(const float* __restrict__ Xres, int mode)
{
    __shared__ __align__(16) __nv_bfloat16 sA[2][2][128 * 16];
    __shared__ __align__(16) __nv_bfloat16 sB[2][2][128 * 16];

    const int tid  = threadIdx.x;
    const int wid  = tid >> 5, lane = tid & 31;
    const int g    = lane >> 2, tg = lane & 3;
    const int m0   = blockIdx.y * 128;
    const int n0g  = blockIdx.x * 128;
    const int mo   = (wid >> 2) * 64;     // warp row offset in tile
    const int no   = (wid & 3) * 32;      // warp col offset in tile

    const __nv_bfloat16* Ahi = mode ? g_chi : g_xhi;
    const __nv_bfloat16* Alo = mode ? g_clo : g_xlo;
    const __nv_bfloat16* Bhi = mode ? g_wohi : g_bthi;
    const __nv_bfloat16* Blo = mode ? g_wolo : g_btlo;

    // loaders: thread covers one 8-bf16 segment; row = tid/2, seg = (tid&1)*8
    const int lrow = tid >> 1;
    const int lseg = (tid & 1) * 8;
    const __nv_bfloat16* pAhi = Ahi + (size_t)(m0 + lrow) * Dn + lseg;
    const __nv_bfloat16* pAlo = Alo + (size_t)(m0 + lrow) * Dn + lseg;
    const __nv_bfloat16* pBhi = Bhi + (size_t)(n0g + lrow) * Dn + lseg;
    const __nv_bfloat16* pBlo = Blo + (size_t)(n0g + lrow) * Dn + lseg;
    const int soff = lrow * 16 + lseg;

    float c[4][4][4];
    #pragma unroll
    for (int i = 0; i < 4; i++)
        #pragma unroll
        for (int j = 0; j < 4; j++)
            #pragma unroll
            for (int r = 0; r < 4; r++) c[i][j][r] = 0.f;

    // prologue: stage 0
    *(uint4*)&sA[0][0][soff] = *(const uint4*)pAhi;
    *(uint4*)&sA[0][1][soff] = *(const uint4*)pAlo;
    *(uint4*)&sB[0][0][soff] = *(const uint4*)pBhi;
    *(uint4*)&sB[0][1][soff] = *(const uint4*)pBlo;
    __syncthreads();

    const int NK = Dn / 16;   // 64
    for (int ks = 0; ks < NK; ks++) {
        const int cur = ks & 1;

        uint4 va, vb, vc, vd;
        if (ks < NK - 1) {
            const int k0 = (ks + 1) * 16;
            va = *(const uint4*)(pAhi + k0);
            vb = *(const uint4*)(pAlo + k0);
            vc = *(const uint4*)(pBhi + k0);
            vd = *(const uint4*)(pBlo + k0);
        }

        // load fragments
        uint32_t a[2][4][4];
        #pragma unroll
        for (int sp = 0; sp < 2; sp++) {
            const __nv_bfloat16* base = &sA[cur][sp][0];
            #pragma unroll
            for (int i = 0; i < 4; i++) {
                int r = (mo + i * 16 + g) * 16 + tg * 2;
                a[sp][i][0] = *(const uint32_t*)&base[r];
                a[sp][i][1] = *(const uint32_t*)&base[r + 8 * 16];
                a[sp][i][2] = *(const uint32_t*)&base[r + 8];
                a[sp][i][3] = *(const uint32_t*)&base[r + 8 * 16 + 8];
            }
        }
        uint32_t b[2][4][2];
        #pragma unroll
        for (int sp = 0; sp < 2; sp++) {
            const __nv_bfloat16* base = &sB[cur][sp][0];
            #pragma unroll
            for (int j = 0; j < 4; j++) {
                int r = (no + j * 8 + g) * 16 + tg * 2;
                b[sp][j][0] = *(const uint32_t*)&base[r];
                b[sp][j][1] = *(const uint32_t*)&base[r + 8];
            }
        }

        // 3-pass MMAs
        #pragma unroll
        for (int i = 0; i < 4; i++)
            #pragma unroll
            for (int j = 0; j < 4; j++) {
                mma16816(c[i][j], a[0][i], b[0][j]);   // hi*hi
                mma16816(c[i][j], a[0][i], b[1][j]);   // hi*lo
                mma16816(c[i][j], a[1][i], b[0][j]);   // lo*hi
            }

        if (ks < NK - 1) {
            const int nb = cur ^ 1;
            *(uint4*)&sA[nb][0][soff] = va;
            *(uint4*)&sA[nb][1][soff] = vb;
            *(uint4*)&sB[nb][0][soff] = vc;
            *(uint4*)&sB[nb][1][soff] = vd;
            __syncthreads();
        }
    }

    // epilogue
    float* OUT;
    int nbase;
    if (mode == 0) {
        int sel = n0g >> 10;
        OUT = (sel == 0) ? g_q : (sel == 1 ? g_k : g_v);
        nbase = n0g & 1023;
    } else {
        OUT = g_res;
        nbase = n0g;
    }

    #pragma unroll
    for (int i = 0; i < 4; i++) {
        #pragma unroll
        for (int j = 0; j < 4; j++) {
            const int r0  = m0 + mo + i * 16 + g;
            const int col = nbase + no + j * 8 + tg * 2;
            size_t o0 = (size_t)r0 * Dn + col;
            size_t o1 = (size_t)(r0 + 8) * Dn + col;
            float2 v0 = make_float2(c[i][j][0], c[i][j][1]);
            float2 v1 = make_float2(c[i][j][2], c[i][j][3]);
            if (mode == 1) {
                float2 x0 = *(const float2*)(Xres + o0);
                float2 x1 = *(const float2*)(Xres + o1);
                v0.x += x0.x; v0.y += x0.y;
                v1.x += x1.x; v1.y += x1.y;
            }
            *(float2*)(OUT + o0) = v0;
            *(float2*)(OUT + o1) = v1;
        }
    }
}

// ======================== attention (unchanged) ==============================
__global__ __launch_bounds__(256) void attn_k(const int* __restrict__ mask)
{
    extern __shared__ float sh[];
    float* sQ  = sh;
    float* sS  = sh + QT * 64;
    float* sVT = sS + QT * Sn;

    const int tid  = threadIdx.x;
    const int blk  = blockIdx.x;
    const int tile = blk % (Sn / QT);
    const int h    = (blk / (Sn / QT)) % Hn;
    const int b    = blk / ((Sn / QT) * Hn);
    const int s0   = tile * QT;

    {
        int j  = tid / 16;
        int d4 = (tid % 16) * 4;
        const float* qp = g_q + ((size_t)(b * Sn + s0 + j)) * Dn + h * DKn + d4;
        *(float4*)&sQ[j * 64 + d4] = *(const float4*)qp;
    }
    __syncthreads();

    const float scale = 0.125f;
    for (int c = 0; c < 4; c++) {
        const int t = c * 256 + tid;
        const float* kp = g_k + ((size_t)(b * Sn + t)) * Dn + h * DKn;
        float kreg[64];
        #pragma unroll
        for (int i = 0; i < 16; i++)
            *(float4*)&kreg[i * 4] = *(const float4*)(kp + i * 4);

        #pragma unroll
        for (int j = 0; j < QT; j++) {
            float s = 0.f;
            #pragma unroll
            for (int i = 0; i < 16; i++) {
                float4 qv = *(const float4*)&sQ[j * 64 + i * 4];
                s += qv.x * kreg[i * 4 + 0];
                s += qv.y * kreg[i * 4 + 1];
                s += qv.z * kreg[i * 4 + 2];
                s += qv.w * kreg[i * 4 + 3];
            }
            int m = mask[((size_t)(b * Sn) + (s0 + j)) * Sn + t];
            sS[j * Sn + t] = (m != 0) ? s * scale : -1e9f;
        }
    }
    __syncthreads();

    const int w = tid / 32, lane = tid % 32;
    #pragma unroll
    for (int rr = 0; rr < 2; rr++) {
        float* row = &sS[(w * 2 + rr) * Sn];
        float mx = -1e30f;
        #pragma unroll
        for (int i = 0; i < 32; i++) mx = fmaxf(mx, row[lane + i * 32]);
        #pragma unroll
        for (int o = 16; o > 0; o >>= 1)
            mx = fmaxf(mx, __shfl_xor_sync(0xffffffffu, mx, o));
        float sum = 0.f;
        #pragma unroll
        for (int i = 0; i < 32; i++) {
            float p = __expf(row[lane + i * 32] - mx);
            row[lane + i * 32] = p;
            sum += p;
        }
        #pragma unroll
        for (int o = 16; o > 0; o >>= 1)
            sum += __shfl_xor_sync(0xffffffffu, sum, o);
        float inv = 1.f / sum;
        #pragma unroll
        for (int i = 0; i < 32; i++) row[lane + i * 32] *= inv;
    }

    float a00 = 0.f, a01 = 0.f, a10 = 0.f, a11 = 0.f;
    const int q0 = w * 2, d0 = lane, d1 = lane + 32;

    for (int c = 0; c < 4; c++) {
        __syncthreads();
        {
            const int t = c * 256 + tid;
            const float* vp = g_v + ((size_t)(b * Sn + t)) * Dn + h * DKn;
            #pragma unroll
            for (int i = 0; i < 16; i++) {
                float4 v = *(const float4*)(vp + i * 4);
                sVT[(i * 4 + 0) * VSTR + tid] = v.x;
                sVT[(i * 4 + 1) * VSTR + tid] = v.y;
                sVT[(i * 4 + 2) * VSTR + tid] = v.z;
                sVT[(i * 4 + 3) * VSTR + tid] = v.w;
            }
        }
        __syncthreads();

        const float* P0 = &sS[q0 * Sn + c * 256];
        const float* P1 = &sS[(q0 + 1) * Sn + c * 256];
        const float* V0 = &sVT[(size_t)d0 * VSTR];
        const float* V1 = &sVT[(size_t)d1 * VSTR];
        #pragma unroll 8
        for (int kk = 0; kk < 256; kk += 4) {
            float4 p0 = *(const float4*)(P0 + kk);
            float4 p1 = *(const float4*)(P1 + kk);
            float4 v0 = *(const float4*)(V0 + kk);
            float4 v1 = *(const float4*)(V1 + kk);
            a00 += p0.x * v0.x + p0.y * v0.y + p0.z * v0.z + p0.w * v0.w;
            a01 += p0.x * v1.x + p0.y * v1.y + p0.z * v1.z + p0.w * v1.w;
            a10 += p1.x * v0.x + p1.y * v0.y + p1.z * v0.z + p1.w * v0.w;
            a11 += p1.x * v1.x + p1.y * v1.y + p1.z * v1.z + p1.w * v1.w;
        }
    }

    float* cp = g_ctx + ((size_t)(b * Sn + s0 + q0)) * Dn + h * DKn;
    cp[d0]      = a00;
    cp[d1]      = a01;
    cp[Dn + d0] = a10;
    cp[Dn + d1] = a11;
}

// ======================== LayerNorm ==========================================
__global__ __launch_bounds__(256) void ln_partial_k()
{
    const int blk = blockIdx.x;
    const int b   = blk / 32;
    const int seg = blk % 32;
    const float* base = g_res + (size_t)b * Sn * Dn + (size_t)seg * 32768;

    float s = 0.f, s2 = 0.f;
    for (int i = threadIdx.x; i < 32768; i += 256) {
        float v = base[i];
        s += v;
        s2 += v * v;
    }
    __shared__ double sh1[256], sh2[256];
    sh1[threadIdx.x] = (double)s;
    sh2[threadIdx.x] = (double)s2;
    __syncthreads();
    for (int o = 128; o > 0; o >>= 1) {
        if (threadIdx.x < o) {
            sh1[threadIdx.x] += sh1[threadIdx.x + o];
            sh2[threadIdx.x] += sh2[threadIdx.x + o];
        }
        __syncthreads();
    }
    if (threadIdx.x == 0) {
        g_part[blk * 2 + 0] = sh1[0];
        g_part[blk * 2 + 1] = sh2[0];
    }
}

__global__ void ln_finish_k()
{
    const int b = blockIdx.x;
    const int l = threadIdx.x;
    __shared__ double sh[64];
    sh[l]      = g_part[(b * 32 + l) * 2 + 0];
    sh[32 + l] = g_part[(b * 32 + l) * 2 + 1];
    __syncthreads();
    if (l == 0) {
        double S = 0.0, S2 = 0.0;
        for (int i = 0; i < 32; i++) { S += sh[i]; S2 += sh[32 + i]; }
        const double N = (double)Sn * (double)Dn;
        double mean = S / N;
        double var  = S2 / N - mean * mean;
        g_stats[b * 2 + 0] = (float)mean;
        g_stats[b * 2 + 1] = (float)(1.0 / sqrt(var + 1e-5));
    }
}

__global__ __launch_bounds__(256) void ln_norm_k(float* __restrict__ out)
{
    const int idx = blockIdx.x * 256 + threadIdx.x;
    const size_t i4 = (size_t)idx * 4;
    const int b = (int)(i4 >> 20);
    const float mean = g_stats[b * 2 + 0];
    const float istd = g_stats[b * 2 + 1];
    float4 v = *(const float4*)&g_res[i4];
    v.x = (v.x - mean) * istd;
    v.y = (v.y - mean) * istd;
    v.z = (v.z - mean) * istd;
    v.w = (v.w - mean) * istd;
    *(float4*)&out[i4] = v;
}

// =============================================================================
extern "C" void kernel_launch(void* const* d_in, const int* in_sizes, int n_in,
                              void* d_out, int out_size)
{
    const int*   mask = (const int*)  d_in[0];
    const float* x    = (const float*)d_in[1];
    const float* wq   = (const float*)d_in[2];
    const float* wk   = (const float*)d_in[3];
    const float* wv   = (const float*)d_in[4];
    const float* wo   = (const float*)d_in[5];
    float* out = (float*)d_out;

    const int smem_attn = (QT * 64 + QT * Sn + 64 * VSTR) * (int)sizeof(float);
    cudaFuncSetAttribute(attn_k, cudaFuncAttributeMaxDynamicSharedMemorySize, smem_attn);

    // 0) bf16 split conversions
    cvt_split_k<<<(Bn * Sn * Dn) / (256 * 4), 256>>>(x, 0);
    cvt_wqkv_k<<<(3 * Dn * Dn) / 256, 256>>>(wq, wk, wv);
    cvt_wo_k<<<dim3(Dn / 32, Dn / 32), dim3(32, 8)>>>(wo);

    // 1) fused QKV projection (HMMA split-bf16)
    gemm_mma_k<<<dim3(24, 64), 256>>>(nullptr, 0);

    // 2) attention
    attn_k<<<Bn * Hn * (Sn / QT), 256, smem_attn>>>(mask);

    // 3) output projection + residual (HMMA split-bf16)
    cvt_split_k<<<(Bn * Sn * Dn) / (256 * 4), 256>>>(nullptr, 1);
    gemm_mma_k<<<dim3(8, 64), 256>>>(x, 1);

    // 4) layernorm over (S, D) per batch
    ln_partial_k<<<Bn * 32, 256>>>();
    ln_finish_k<<<Bn, 32>>>();
    ln_norm_k<<<(Bn * Sn * Dn) / (256 * 4), 256>>>(out);
}

// round 10
// speedup vs baseline: 1.0679x; 1.0010x over previous
#include <cuda_runtime.h>
#include <cuda_bf16.h>
#include <math.h>
#include <stdint.h>

#define Bn  8
#define Sn  1024
#define Dn  1024
#define Hn  16
#define DKn 64
#define QT  16
#define VSTR 260

// ---------------- scratch (device globals; no allocation allowed) -------------
__device__ __align__(256) float g_q  [Bn*Sn*Dn];
__device__ __align__(256) float g_k  [Bn*Sn*Dn];
__device__ __align__(256) float g_v  [Bn*Sn*Dn];
__device__ __align__(256) float g_ctx[Bn*Sn*Dn];
__device__ __align__(256) float g_res[Bn*Sn*Dn];
__device__ double g_part[Bn*32*2];
__device__ float g_stats[Bn*2];

// bf16 split scratch
__device__ __align__(256) __nv_bfloat16 g_xhi[Bn*Sn*Dn];
__device__ __align__(256) __nv_bfloat16 g_xlo[Bn*Sn*Dn];
__device__ __align__(256) __nv_bfloat16 g_chi[Bn*Sn*Dn];
__device__ __align__(256) __nv_bfloat16 g_clo[Bn*Sn*Dn];
__device__ __align__(256) __nv_bfloat16 g_bthi[3*Dn*Dn];   // qkv weights, Bt[n][k]
__device__ __align__(256) __nv_bfloat16 g_btlo[3*Dn*Dn];
__device__ __align__(256) __nv_bfloat16 g_wohi[Dn*Dn];     // wo^T, Bt[n][k]=WO[k][n]
__device__ __align__(256) __nv_bfloat16 g_wolo[Dn*Dn];

// ---------------- mma.sync helper (sm_80+ path, compiles on compute_103) ------
__device__ __forceinline__ void mma16816(float* c, const uint32_t* a, const uint32_t* b)
{
    asm volatile(
        "mma.sync.aligned.m16n8k16.row.col.f32.bf16.bf16.f32 "
        "{%0,%1,%2,%3}, {%4,%5,%6,%7}, {%8,%9}, {%0,%1,%2,%3};"
        : "+f"(c[0]), "+f"(c[1]), "+f"(c[2]), "+f"(c[3])
        : "r"(a[0]), "r"(a[1]), "r"(a[2]), "r"(a[3]), "r"(b[0]), "r"(b[1]));
}

// ======================== conversion kernels =================================
__global__ __launch_bounds__(256) void cvt_split_k(const float* __restrict__ xext, int which)
{
    const float* src = which ? g_ctx : xext;
    __nv_bfloat16* hi = which ? g_chi : g_xhi;
    __nv_bfloat16* lo = which ? g_clo : g_xlo;
    size_t i = ((size_t)blockIdx.x * 256 + threadIdx.x) * 4;
    float4 v = *(const float4*)(src + i);
    __nv_bfloat16 h0 = __float2bfloat16(v.x), l0 = __float2bfloat16(v.x - __bfloat162float(h0));
    __nv_bfloat16 h1 = __float2bfloat16(v.y), l1 = __float2bfloat16(v.y - __bfloat162float(h1));
    __nv_bfloat16 h2 = __float2bfloat16(v.z), l2 = __float2bfloat16(v.z - __bfloat162float(h2));
    __nv_bfloat16 h3 = __float2bfloat16(v.w), l3 = __float2bfloat16(v.w - __bfloat162float(h3));
    *(__nv_bfloat162*)(hi + i)     = __halves2bfloat162(h0, h1);
    *(__nv_bfloat162*)(hi + i + 2) = __halves2bfloat162(h2, h3);
    *(__nv_bfloat162*)(lo + i)     = __halves2bfloat162(l0, l1);
    *(__nv_bfloat162*)(lo + i + 2) = __halves2bfloat162(l2, l3);
}

// Bt_qkv[n][k] = Wsel[h][k][kk], n in [0,3072), h=(n%1024)/64, kk=n%64
__global__ __launch_bounds__(256) void cvt_wqkv_k(const float* __restrict__ WQ,
                                                  const float* __restrict__ WK,
                                                  const float* __restrict__ WV)
{
    size_t idx = (size_t)blockIdx.x * 256 + threadIdx.x;   // over 3072*1024
    int k = (int)(idx & 1023);
    int n = (int)(idx >> 10);
    int within = n & 1023, sel = n >> 10;
    const float* W = (sel == 0) ? WQ : (sel == 1 ? WK : WV);
    float w = W[(size_t)(within >> 6) * (Dn * DKn) + (size_t)k * DKn + (within & 63)];
    __nv_bfloat16 h = __float2bfloat16(w);
    g_bthi[idx] = h;
    g_btlo[idx] = __float2bfloat16(w - __bfloat162float(h));
}

// Bt_wo[n][k] = WO[k][n]  (tiled transpose + split)
__global__ __launch_bounds__(256) void cvt_wo_k(const float* __restrict__ WO)
{
    __shared__ float t[32][33];
    const int x = threadIdx.x, y = threadIdx.y;       // (32, 8)
    const int bx = blockIdx.x, by = blockIdx.y;
    #pragma unroll
    for (int i = 0; i < 4; i++)
        t[y + i * 8][x] = WO[(size_t)(by * 32 + y + i * 8) * Dn + bx * 32 + x];
    __syncthreads();
    #pragma unroll
    for (int i = 0; i < 4; i++) {
        float w = t[x][y + i * 8];
        __nv_bfloat16 h = __float2bfloat16(w);
        size_t o = (size_t)(bx * 32 + y + i * 8) * Dn + by * 32 + x;
        g_wohi[o] = h;
        g_wolo[o] = __float2bfloat16(w - __bfloat162float(h));
    }
}

// ======================== split-bf16 HMMA GEMM ===============================
// C[M x N] = A * Bt^T (Bt is [N][K] K-major). 128x128 tile, 8 warps (2x4),
// warp tile 64x32 (4x4 m16n8k16 frags), K-step 16, double-buffered SMEM.
// 3-pass split accumulate: Ahi*Bhi + Ahi*Blo + Alo*Bhi (fp32 accum).
// mode 0: qkv (OUT among g_q/g_k/g_v by n block); mode 1: out proj + residual.
__global__ __launch_bounds__(256, 1) void gemm_mma_k(const float* __restrict__ Xres, int mode)
{
    __shared__ __align__(16) __nv_bfloat16 sA[2][2][128 * 16];
    __shared__ __align__(16) __nv_bfloat16 sB[2][2][128 * 16];

    const int tid  = threadIdx.x;
    const int wid  = tid >> 5, lane = tid & 31;
    const int g    = lane >> 2, tg = lane & 3;
    const int m0   = blockIdx.y * 128;
    const int n0g  = blockIdx.x * 128;
    const int mo   = (wid >> 2) * 64;     // warp row offset in tile
    const int no   = (wid & 3) * 32;      // warp col offset in tile

    const __nv_bfloat16* Ahi = mode ? g_chi : g_xhi;
    const __nv_bfloat16* Alo = mode ? g_clo : g_xlo;
    const __nv_bfloat16* Bhi = mode ? g_wohi : g_bthi;
    const __nv_bfloat16* Blo = mode ? g_wolo : g_btlo;

    // loaders: thread covers one 8-bf16 segment; row = tid/2, seg = (tid&1)*8
    const int lrow = tid >> 1;
    const int lseg = (tid & 1) * 8;
    const __nv_bfloat16* pAhi = Ahi + (size_t)(m0 + lrow) * Dn + lseg;
    const __nv_bfloat16* pAlo = Alo + (size_t)(m0 + lrow) * Dn + lseg;
    const __nv_bfloat16* pBhi = Bhi + (size_t)(n0g + lrow) * Dn + lseg;
    const __nv_bfloat16* pBlo = Blo + (size_t)(n0g + lrow) * Dn + lseg;
    const int soff = lrow * 16 + lseg;

    float c[4][4][4];
    #pragma unroll
    for (int i = 0; i < 4; i++)
        #pragma unroll
        for (int j = 0; j < 4; j++)
            #pragma unroll
            for (int r = 0; r < 4; r++) c[i][j][r] = 0.f;

    // prologue: stage 0
    *(uint4*)&sA[0][0][soff] = *(const uint4*)pAhi;
    *(uint4*)&sA[0][1][soff] = *(const uint4*)pAlo;
    *(uint4*)&sB[0][0][soff] = *(const uint4*)pBhi;
    *(uint4*)&sB[0][1][soff] = *(const uint4*)pBlo;
    __syncthreads();

    const int NK = Dn / 16;   // 64
    for (int ks = 0; ks < NK; ks++) {
        const int cur = ks & 1;

        uint4 va, vb, vc, vd;
        if (ks < NK - 1) {
            const int k0 = (ks + 1) * 16;
            va = *(const uint4*)(pAhi + k0);
            vb = *(const uint4*)(pAlo + k0);
            vc = *(const uint4*)(pBhi + k0);
            vd = *(const uint4*)(pBlo + k0);
        }

        // load fragments
        uint32_t a[2][4][4];
        #pragma unroll
        for (int sp = 0; sp < 2; sp++) {
            const __nv_bfloat16* base = &sA[cur][sp][0];
            #pragma unroll
            for (int i = 0; i < 4; i++) {
                int r = (mo + i * 16 + g) * 16 + tg * 2;
                a[sp][i][0] = *(const uint32_t*)&base[r];
                a[sp][i][1] = *(const uint32_t*)&base[r + 8 * 16];
                a[sp][i][2] = *(const uint32_t*)&base[r + 8];
                a[sp][i][3] = *(const uint32_t*)&base[r + 8 * 16 + 8];
            }
        }
        uint32_t b[2][4][2];
        #pragma unroll
        for (int sp = 0; sp < 2; sp++) {
            const __nv_bfloat16* base = &sB[cur][sp][0];
            #pragma unroll
            for (int j = 0; j < 4; j++) {
                int r = (no + j * 8 + g) * 16 + tg * 2;
                b[sp][j][0] = *(const uint32_t*)&base[r];
                b[sp][j][1] = *(const uint32_t*)&base[r + 8];
            }
        }

        // 3-pass MMAs
        #pragma unroll
        for (int i = 0; i < 4; i++)
            #pragma unroll
            for (int j = 0; j < 4; j++) {
                mma16816(c[i][j], a[0][i], b[0][j]);   // hi*hi
                mma16816(c[i][j], a[0][i], b[1][j]);   // hi*lo
                mma16816(c[i][j], a[1][i], b[0][j]);   // lo*hi
            }

        if (ks < NK - 1) {
            const int nb = cur ^ 1;
            *(uint4*)&sA[nb][0][soff] = va;
            *(uint4*)&sA[nb][1][soff] = vb;
            *(uint4*)&sB[nb][0][soff] = vc;
            *(uint4*)&sB[nb][1][soff] = vd;
            __syncthreads();
        }
    }

    // epilogue
    float* OUT;
    int nbase;
    if (mode == 0) {
        int sel = n0g >> 10;
        OUT = (sel == 0) ? g_q : (sel == 1 ? g_k : g_v);
        nbase = n0g & 1023;
    } else {
        OUT = g_res;
        nbase = n0g;
    }

    #pragma unroll
    for (int i = 0; i < 4; i++) {
        #pragma unroll
        for (int j = 0; j < 4; j++) {
            const int r0  = m0 + mo + i * 16 + g;
            const int col = nbase + no + j * 8 + tg * 2;
            size_t o0 = (size_t)r0 * Dn + col;
            size_t o1 = (size_t)(r0 + 8) * Dn + col;
            float2 v0 = make_float2(c[i][j][0], c[i][j][1]);
            float2 v1 = make_float2(c[i][j][2], c[i][j][3]);
            if (mode == 1) {
                float2 x0 = *(const float2*)(Xres + o0);
                float2 x1 = *(const float2*)(Xres + o1);
                v0.x += x0.x; v0.y += x0.y;
                v1.x += x1.x; v1.y += x1.y;
            }
            *(float2*)(OUT + o0) = v0;
            *(float2*)(OUT + o1) = v1;
        }
    }
}

// ======================== attention (unchanged) ==============================
__global__ __launch_bounds__(256) void attn_k(const int* __restrict__ mask)
{
    extern __shared__ float sh[];
    float* sQ  = sh;
    float* sS  = sh + QT * 64;
    float* sVT = sS + QT * Sn;

    const int tid  = threadIdx.x;
    const int blk  = blockIdx.x;
    const int tile = blk % (Sn / QT);
    const int h    = (blk / (Sn / QT)) % Hn;
    const int b    = blk / ((Sn / QT) * Hn);
    const int s0   = tile * QT;

    {
        int j  = tid / 16;
        int d4 = (tid % 16) * 4;
        const float* qp = g_q + ((size_t)(b * Sn + s0 + j)) * Dn + h * DKn + d4;
        *(float4*)&sQ[j * 64 + d4] = *(const float4*)qp;
    }
    __syncthreads();

    const float scale = 0.125f;
    for (int c = 0; c < 4; c++) {
        const int t = c * 256 + tid;
        const float* kp = g_k + ((size_t)(b * Sn + t)) * Dn + h * DKn;
        float kreg[64];
        #pragma unroll
        for (int i = 0; i < 16; i++)
            *(float4*)&kreg[i * 4] = *(const float4*)(kp + i * 4);

        #pragma unroll
        for (int j = 0; j < QT; j++) {
            float s = 0.f;
            #pragma unroll
            for (int i = 0; i < 16; i++) {
                float4 qv = *(const float4*)&sQ[j * 64 + i * 4];
                s += qv.x * kreg[i * 4 + 0];
                s += qv.y * kreg[i * 4 + 1];
                s += qv.z * kreg[i * 4 + 2];
                s += qv.w * kreg[i * 4 + 3];
            }
            int m = mask[((size_t)(b * Sn) + (s0 + j)) * Sn + t];
            sS[j * Sn + t] = (m != 0) ? s * scale : -1e9f;
        }
    }
    __syncthreads();

    const int w = tid / 32, lane = tid % 32;
    #pragma unroll
    for (int rr = 0; rr < 2; rr++) {
        float* row = &sS[(w * 2 + rr) * Sn];
        float mx = -1e30f;
        #pragma unroll
        for (int i = 0; i < 32; i++) mx = fmaxf(mx, row[lane + i * 32]);
        #pragma unroll
        for (int o = 16; o > 0; o >>= 1)
            mx = fmaxf(mx, __shfl_xor_sync(0xffffffffu, mx, o));
        float sum = 0.f;
        #pragma unroll
        for (int i = 0; i < 32; i++) {
            float p = __expf(row[lane + i * 32] - mx);
            row[lane + i * 32] = p;
            sum += p;
        }
        #pragma unroll
        for (int o = 16; o > 0; o >>= 1)
            sum += __shfl_xor_sync(0xffffffffu, sum, o);
        float inv = 1.f / sum;
        #pragma unroll
        for (int i = 0; i < 32; i++) row[lane + i * 32] *= inv;
    }

    float a00 = 0.f, a01 = 0.f, a10 = 0.f, a11 = 0.f;
    const int q0 = w * 2, d0 = lane, d1 = lane + 32;

    for (int c = 0; c < 4; c++) {
        __syncthreads();
        {
            const int t = c * 256 + tid;
            const float* vp = g_v + ((size_t)(b * Sn + t)) * Dn + h * DKn;
            #pragma unroll
            for (int i = 0; i < 16; i++) {
                float4 v = *(const float4*)(vp + i * 4);
                sVT[(i * 4 + 0) * VSTR + tid] = v.x;
                sVT[(i * 4 + 1) * VSTR + tid] = v.y;
                sVT[(i * 4 + 2) * VSTR + tid] = v.z;
                sVT[(i * 4 + 3) * VSTR + tid] = v.w;
            }
        }
        __syncthreads();

        const float* P0 = &sS[q0 * Sn + c * 256];
        const float* P1 = &sS[(q0 + 1) * Sn + c * 256];
        const float* V0 = &sVT[(size_t)d0 * VSTR];
        const float* V1 = &sVT[(size_t)d1 * VSTR];
        #pragma unroll 8
        for (int kk = 0; kk < 256; kk += 4) {
            float4 p0 = *(const float4*)(P0 + kk);
            float4 p1 = *(const float4*)(P1 + kk);
            float4 v0 = *(const float4*)(V0 + kk);
            float4 v1 = *(const float4*)(V1 + kk);
            a00 += p0.x * v0.x + p0.y * v0.y + p0.z * v0.z + p0.w * v0.w;
            a01 += p0.x * v1.x + p0.y * v1.y + p0.z * v1.z + p0.w * v1.w;
            a10 += p1.x * v0.x + p1.y * v0.y + p1.z * v0.z + p1.w * v0.w;
            a11 += p1.x * v1.x + p1.y * v1.y + p1.z * v1.z + p1.w * v1.w;
        }
    }

    float* cp = g_ctx + ((size_t)(b * Sn + s0 + q0)) * Dn + h * DKn;
    cp[d0]      = a00;
    cp[d1]      = a01;
    cp[Dn + d0] = a10;
    cp[Dn + d1] = a11;
}

// ======================== LayerNorm ==========================================
__global__ __launch_bounds__(256) void ln_partial_k()
{
    const int blk = blockIdx.x;
    const int b   = blk / 32;
    const int seg = blk % 32;
    const float* base = g_res + (size_t)b * Sn * Dn + (size_t)seg * 32768;

    float s = 0.f, s2 = 0.f;
    for (int i = threadIdx.x; i < 32768; i += 256) {
        float v = base[i];
        s += v;
        s2 += v * v;
    }
    __shared__ double sh1[256], sh2[256];
    sh1[threadIdx.x] = (double)s;
    sh2[threadIdx.x] = (double)s2;
    __syncthreads();
    for (int o = 128; o > 0; o >>= 1) {
        if (threadIdx.x < o) {
            sh1[threadIdx.x] += sh1[threadIdx.x + o];
            sh2[threadIdx.x] += sh2[threadIdx.x + o];
        }
        __syncthreads();
    }
    if (threadIdx.x == 0) {
        g_part[blk * 2 + 0] = sh1[0];
        g_part[blk * 2 + 1] = sh2[0];
    }
}

__global__ void ln_finish_k()
{
    const int b = blockIdx.x;
    const int l = threadIdx.x;
    __shared__ double sh[64];
    sh[l]      = g_part[(b * 32 + l) * 2 + 0];
    sh[32 + l] = g_part[(b * 32 + l) * 2 + 1];
    __syncthreads();
    if (l == 0) {
        double S = 0.0, S2 = 0.0;
        for (int i = 0; i < 32; i++) { S += sh[i]; S2 += sh[32 + i]; }
        const double N = (double)Sn * (double)Dn;
        double mean = S / N;
        double var  = S2 / N - mean * mean;
        g_stats[b * 2 + 0] = (float)mean;
        g_stats[b * 2 + 1] = (float)(1.0 / sqrt(var + 1e-5));
    }
}

__global__ __launch_bounds__(256) void ln_norm_k(float* __restrict__ out)
{
    const int idx = blockIdx.x * 256 + threadIdx.x;
    const size_t i4 = (size_t)idx * 4;
    const int b = (int)(i4 >> 20);
    const float mean = g_stats[b * 2 + 0];
    const float istd = g_stats[b * 2 + 1];
    float4 v = *(const float4*)&g_res[i4];
    v.x = (v.x - mean) * istd;
    v.y = (v.y - mean) * istd;
    v.z = (v.z - mean) * istd;
    v.w = (v.w - mean) * istd;
    *(float4*)&out[i4] = v;
}

// =============================================================================
extern "C" void kernel_launch(void* const* d_in, const int* in_sizes, int n_in,
                              void* d_out, int out_size)
{
    const int*   mask = (const int*)  d_in[0];
    const float* x    = (const float*)d_in[1];
    const float* wq   = (const float*)d_in[2];
    const float* wk   = (const float*)d_in[3];
    const float* wv   = (const float*)d_in[4];
    const float* wo   = (const float*)d_in[5];
    float* out = (float*)d_out;

    const int smem_attn = (QT * 64 + QT * Sn + 64 * VSTR) * (int)sizeof(float);
    cudaFuncSetAttribute(attn_k, cudaFuncAttributeMaxDynamicSharedMemorySize, smem_attn);

    // 0) bf16 split conversions
    cvt_split_k<<<(Bn * Sn * Dn) / (256 * 4), 256>>>(x, 0);
    cvt_wqkv_k<<<(3 * Dn * Dn) / 256, 256>>>(wq, wk, wv);
    cvt_wo_k<<<dim3(Dn / 32, Dn / 32), dim3(32, 8)>>>(wo);

    // 1) fused QKV projection (HMMA split-bf16)
    gemm_mma_k<<<dim3(24, 64), 256>>>(nullptr, 0);

    // 2) attention
    attn_k<<<Bn * Hn * (Sn / QT), 256, smem_attn>>>(mask);

    // 3) output projection + residual (HMMA split-bf16)
    cvt_split_k<<<(Bn * Sn * Dn) / (256 * 4), 256>>>(nullptr, 1);
    gemm_mma_k<<<dim3(8, 64), 256>>>(x, 1);

    // 4) layernorm over (S, D) per batch
    ln_partial_k<<<Bn * 32, 256>>>();
    ln_finish_k<<<Bn, 32>>>();
    ln_norm_k<<<(Bn * Sn * Dn) / (256 * 4), 256>>>(out);
}